// round 5
// baseline (speedup 1.0000x reference)
#include <cuda_runtime.h>
#include <cuda_bf16.h>
#include <cstdint>

// Problem constants
#define B_DIM 4
#define S_DIM 256
#define V_DIM 50257
#define D_DIM 768
#define ROWS (B_DIM * S_DIM)                    // 1024
#define TOTAL_ELEMS ((long long)ROWS * V_DIM)   // 51,463,168 (divisible by 4)
#define N4 ((unsigned int)(TOTAL_ELEMS / 4))    // 12,865,792 float4 loads
#define D4 (D_DIM / 4)                          // 192 float4 per output row

// ---------------------------------------------------------------------------
// Fused kernel: stream the one_hot tensor as float4; the thread that finds a
// row's single nonzero immediately writes out[row][:] = val * weight[col][:].
// The 1024 finder tails (192 float4 ld+st each) hide behind the 206 MB scan.
// ---------------------------------------------------------------------------
__global__ void __launch_bounds__(256)
scan_fused_kernel(const float4* __restrict__ oh,
                  const float4* __restrict__ weight,
                  float4*       __restrict__ out)
{
    unsigned int tid    = blockIdx.x * blockDim.x + threadIdx.x;
    unsigned int stride = gridDim.x * blockDim.x;

    #pragma unroll 8
    for (unsigned int i = tid; i < N4; i += stride) {
        float4 v = __ldcs(&oh[i]);               // streaming: read-once data

        // Cheap hot-path test: one integer OR over the 4 words.
        // (False positive only on -0.0; the float checks below handle that.)
        unsigned int bx = __float_as_uint(v.x);
        unsigned int by = __float_as_uint(v.y);
        unsigned int bz = __float_as_uint(v.z);
        unsigned int bw = __float_as_uint(v.w);
        if ((bx | by | bz | bw) != 0u) {
            unsigned int base = i * 4u;
            float vals[4] = {v.x, v.y, v.z, v.w};
            #pragma unroll
            for (int k = 0; k < 4; ++k) {
                if (vals[k] != 0.0f) {
                    unsigned int flat = base + (unsigned int)k;
                    unsigned int row  = flat / (unsigned int)V_DIM;  // rare path
                    unsigned int col  = flat - row * (unsigned int)V_DIM;
                    float s = vals[k];

                    const float4* __restrict__ w = weight + (size_t)col * D4;
                    float4*       __restrict__ o = out    + (size_t)row * D4;
                    #pragma unroll 4
                    for (int d = 0; d < D4; ++d) {
                        float4 t = __ldg(&w[d]);
                        float4 r;
                        r.x = s * t.x;
                        r.y = s * t.y;
                        r.z = s * t.z;
                        r.w = s * t.w;
                        o[d] = r;
                    }
                }
            }
        }
    }
}

// ---------------------------------------------------------------------------
// Launch: d_in[0] = one_hot [B,S,V] f32, d_in[1] = weight [V,D] f32.
// Output [B,S,D] f32 — fully written by the 1024 finder threads.
// ---------------------------------------------------------------------------
extern "C" void kernel_launch(void* const* d_in, const int* in_sizes, int n_in,
                              void* d_out, int out_size)
{
    const float4* oh     = (const float4*)d_in[0];
    const float4* weight = (const float4*)d_in[1];
    float4*       out    = (float4*)d_out;

    (void)in_sizes; (void)n_in; (void)out_size;

    scan_fused_kernel<<<2048, 256>>>(oh, weight, out);
}

// round 6
// speedup vs baseline: 1.8082x; 1.8082x over previous
#include <cuda_runtime.h>
#include <cuda_bf16.h>
#include <cstdint>

// Problem constants
#define B_DIM 4
#define S_DIM 256
#define V_DIM 50257
#define D_DIM 768
#define ROWS (B_DIM * S_DIM)                    // 1024
#define TOTAL_ELEMS ((long long)ROWS * V_DIM)   // 51,463,168 (divisible by 4)
#define N4 ((unsigned int)(TOTAL_ELEMS / 4))    // 12,865,792 float4 loads
#define D4 (D_DIM / 4)                          // 192 float4 per output row
#define OUT4 (ROWS * D4)                        // 196,608 output float4s

// Scratch: index and value of the single nonzero per (b,s) row.
__device__ int   g_idx[ROWS];
__device__ float g_val[ROWS];

// ---------------------------------------------------------------------------
// Kernel 1: scan one_hot as a flat float4 stream. Manually batch 8
// independent grid-stride loads into registers BEFORE any test, so ptxas
// front-batches 8 LDG.128 (MLP=8). Rare path does only 2 scalar stores.
// ---------------------------------------------------------------------------
__device__ __forceinline__ void record_hit(float4 v, unsigned int i4)
{
    // i4 = float4 index; exactly one of the 4 lanes is nonzero when called.
    unsigned int base = i4 * 4u;
    float vals[4] = {v.x, v.y, v.z, v.w};
    #pragma unroll
    for (int k = 0; k < 4; ++k) {
        if (vals[k] != 0.0f) {
            unsigned int flat = base + (unsigned int)k;
            unsigned int row  = flat / (unsigned int)V_DIM;   // rare: div ok
            unsigned int col  = flat - row * (unsigned int)V_DIM;
            g_idx[row] = (int)col;
            g_val[row] = vals[k];
        }
    }
}

__device__ __forceinline__ bool nz4(float4 v)
{
    // one_hot values are exactly 0.0f or positive; integer OR test is exact.
    return ((__float_as_uint(v.x) | __float_as_uint(v.y) |
             __float_as_uint(v.z) | __float_as_uint(v.w)) != 0u);
}

__global__ void __launch_bounds__(256)
scan_onehot_kernel(const float4* __restrict__ oh)
{
    unsigned int stride = gridDim.x * blockDim.x;
    unsigned int i      = blockIdx.x * blockDim.x + threadIdx.x;

    // Main loop: batches of 8 independent loads, tests only after all issue.
    for (; i + 7u * stride < N4; i += 8u * stride) {
        float4 v[8];
        #pragma unroll
        for (int k = 0; k < 8; ++k)
            v[k] = oh[i + (unsigned int)k * stride];

        #pragma unroll
        for (int k = 0; k < 8; ++k)
            if (nz4(v[k]))
                record_hit(v[k], i + (unsigned int)k * stride);
    }

    // Tail
    for (; i < N4; i += stride) {
        float4 v = oh[i];
        if (nz4(v))
            record_hit(v, i);
    }
}

// ---------------------------------------------------------------------------
// Kernel 2: one float4 per thread, flat over the whole output.
// out[row][d] = g_val[row] * weight[g_idx[row]][d]
// 768 blocks x 256 threads = 196,608 threads = OUT4 exactly (one wave).
// ---------------------------------------------------------------------------
__global__ void __launch_bounds__(256)
gather_kernel(const float4* __restrict__ weight, float4* __restrict__ out)
{
    unsigned int t   = blockIdx.x * blockDim.x + threadIdx.x;  // < OUT4
    unsigned int row = t / (unsigned int)D4;
    unsigned int d   = t - row * (unsigned int)D4;

    int   idx = g_idx[row];          // L1/L2 broadcast across the row's threads
    float s   = g_val[row];

    float4 w = __ldg(&weight[(size_t)idx * D4 + d]);
    float4 o;
    o.x = s * w.x;
    o.y = s * w.y;
    o.z = s * w.z;
    o.w = s * w.w;
    out[t] = o;
}

// ---------------------------------------------------------------------------
// Launch: d_in[0] = one_hot [B,S,V] f32, d_in[1] = weight [V,D] f32.
// Output [B,S,D] f32.
// ---------------------------------------------------------------------------
extern "C" void kernel_launch(void* const* d_in, const int* in_sizes, int n_in,
                              void* d_out, int out_size)
{
    const float4* oh     = (const float4*)d_in[0];
    const float4* weight = (const float4*)d_in[1];
    float4*       out    = (float4*)d_out;

    (void)in_sizes; (void)n_in; (void)out_size;

    scan_onehot_kernel<<<2048, 256>>>(oh);
    gather_kernel<<<OUT4 / 256, 256>>>(weight, out);
}